// round 13
// baseline (speedup 1.0000x reference)
#include <cuda_runtime.h>
#include <cuda_fp16.h>
#include <cstdint>

#define NB 8192
#define NE 8
#define DIN 1344
#define DH 1024
#define KH (NE * DH)   // 8192
#define DMID 128
#define DOUT 162
#define DOUTP 192      // DOUT padded to tile multiple (rows 162..191 stay zero)
#define RSCL 2048.0f
#define RINV (1.0f / 2048.0f)

// ---------------- device scratch (static; ~362 MB, all zero-initialized) --------
__device__ __align__(256) __half g_Xh [NB * DIN];
__device__ __align__(256) __half g_Xl [NB * DIN];
__device__ __align__(256) __half g_W1th[NE * DH * DIN];   // [e][h][d] hi
__device__ __align__(256) __half g_W1tl[NE * DH * DIN];   // residual*2^11
__device__ __align__(256) __half g_W2th[DMID * KH];       // [n][k]
__device__ __align__(256) __half g_W2tl[DMID * KH];
__device__ __align__(256) __half g_W3t [NE * DH * DMID];  // [e][h][dmid] single
__device__ __align__(256) __half g_W4t [DOUTP * KH];      // [n][k] single, zero-padded rows
__device__ __align__(256) __half g_Hh [(size_t)NB * KH];  // hidden hi (both layers)
__device__ __align__(256) __half g_Hl [(size_t)NB * KH];  // hidden residual*2^11 (layer1)
__device__ __align__(256) float  g_Y  [NB * DMID];        // fp32 y (router input)
__device__ __align__(256) __half g_Yh [NB * DMID];        // half y (GEMM3 A)
__device__ float g_P1[NB * NE];
__device__ float g_coef[NB * NE];
__device__ float g_probs2[NB * NE];

// ---------------- helpers ------------------------------------------------------
__device__ __forceinline__ float gelu_f(float x) {
    return 0.5f * x * (1.0f + erff(x * 0.70710678118654752f));
}
__device__ __forceinline__ void split16(float v, __half& h, __half& l) {
    h = __float2half_rn(v);
    l = __float2half_rn((v - __half2float(h)) * RSCL);
}
__device__ __forceinline__ void cp16(void* smem, const void* gmem) {
    uint32_t s = (uint32_t)__cvta_generic_to_shared(smem);
    asm volatile("cp.async.cg.shared.global [%0], [%1], 16;\n" :: "r"(s), "l"(gmem));
}
__device__ __forceinline__ void cp_commit() { asm volatile("cp.async.commit_group;\n"); }
template <int N>
__device__ __forceinline__ void cp_wait() { asm volatile("cp.async.wait_group %0;\n" :: "n"(N)); }

__device__ __forceinline__ void mma_f16(float* c, const uint32_t* a, const uint32_t* b) {
    asm volatile("mma.sync.aligned.m16n8k16.row.col.f32.f16.f16.f32 "
        "{%0,%1,%2,%3}, {%4,%5,%6,%7}, {%8,%9}, {%0,%1,%2,%3};\n"
        : "+f"(c[0]), "+f"(c[1]), "+f"(c[2]), "+f"(c[3])
        : "r"(a[0]), "r"(a[1]), "r"(a[2]), "r"(a[3]), "r"(b[0]), "r"(b[1]));
}
__device__ __forceinline__ void ldsm_x4(uint32_t& r0, uint32_t& r1, uint32_t& r2, uint32_t& r3,
                                        uint32_t addr) {
    asm volatile("ldmatrix.sync.aligned.m8n8.x4.shared.b16 {%0,%1,%2,%3}, [%4];"
        : "=r"(r0), "=r"(r1), "=r"(r2), "=r"(r3) : "r"(addr));
}

// ---------------- epilogue functors (pairwise: cols n, n+1) --------------------
struct Epi1 {  // layer1 GEMM1: h1s = probs1 * gelu(v + b1) -> split half pair
    const float* b1;
    __device__ void operator()(int m, int n, float v0, float v1) const {
        int e = n >> 10, h = n & 1023;
        float p = g_P1[m * NE + e];
        float w0 = gelu_f(v0 + b1[e * DH + h]) * p;
        float w1 = gelu_f(v1 + b1[e * DH + h + 1]) * p;
        __half h0, l0, h1, l1;
        split16(w0, h0, l0); split16(w1, h1, l1);
        *(__half2*)(g_Hh + (size_t)m * KH + n) = __halves2half2(h0, h1);
        *(__half2*)(g_Hl + (size_t)m * KH + n) = __halves2half2(l0, l1);
    }
};
struct Epi2 {  // layer1 GEMM2: y = gelu(v + sum_e p*b2) -> fp32 + half
    const float* b2;
    __device__ void operator()(int m, int n, float v0, float v1) const {
        float ba = 0.f, bb = 0.f;
        #pragma unroll
        for (int e = 0; e < NE; e++) {
            float p = g_P1[m * NE + e];
            ba += p * b2[e * DMID + n];
            bb += p * b2[e * DMID + n + 1];
        }
        float y0 = gelu_f(v0 + ba), y1 = gelu_f(v1 + bb);
        g_Y[m * DMID + n] = y0;
        g_Y[m * DMID + n + 1] = y1;
        *(__half2*)(g_Yh + m * DMID + n) =
            __halves2half2(__float2half_rn(y0), __float2half_rn(y1));
    }
};
struct Epi3 {  // layer2 GEMM1: h2s = coef * gelu(v + b1) -> single half
    const float* b1;
    __device__ void operator()(int m, int n, float v0, float v1) const {
        int e = n >> 10, h = n & 1023;
        float c = g_coef[m * NE + e];
        float w0 = gelu_f(v0 + b1[e * DH + h]) * c;
        float w1 = gelu_f(v1 + b1[e * DH + h + 1]) * c;
        *(__half2*)(g_Hh + (size_t)m * KH + n) =
            __halves2half2(__float2half_rn(w0), __float2half_rn(w1));
    }
};
struct Epi4 {  // layer2 GEMM2: out = v + sum_e coef*b2 (only n < DOUT written)
    const float* b2;
    float* out;
    __device__ void operator()(int m, int n, float v0, float v1) const {
        #pragma unroll
        for (int t = 0; t < 2; t++) {
            int nn = n + t;
            float vv = t ? v1 : v0;
            if (nn < DOUT) {
                float bias = 0.f;
                #pragma unroll
                for (int e = 0; e < NE; e++) bias += g_coef[m * NE + e] * b2[e * DOUT + nn];
                out[(size_t)m * DOUT + nn] = vv + bias;
            }
        }
    }
};

// ---------------- fp16 tensor-core GEMM (single or scaled-residual x3) ---------
// C[m,n] = sum_k A[m,k]*B[n,k] (B stored n-major [n][k], N padded to tile mult).
// SPLIT: acc1 += Ah*Bh ; acc2 += Ah*Bl + Al*Bh ; final = acc1 + acc2*2^-11.
// 4-stage cp.async pipeline; ALL dynamic smem <= 48KB (no attribute calls).
// Tail uses empty commit groups to keep the pending-group count invariant.
template <int BM, int BN, int BK, int WM, int WN, bool SPLIT, bool DRAIN, class Epi>
__global__ void __launch_bounds__(256) gemm_f16k(
    const __half* __restrict__ Ah_, const __half* __restrict__ Al_, int lda,
    const __half* __restrict__ Bh_, const __half* __restrict__ Bl_, int ldb,
    size_t e_stride, int e_shift, int K, Epi epi)
{
    constexpr int NSTG = 4;
    constexpr int BKP = BK + 8;          // padded row stride (halves)
    constexpr int WTM = BM / WM, WTN = BN / WN;
    constexpr int MT = WTM / 16, NT = WTN / 8;
    static_assert(NT % 2 == 0, "B ldmatrix pairs two n-tiles");
    constexpr int oAl = BM * BKP;
    constexpr int oBh = (SPLIT ? 2 : 1) * BM * BKP;
    constexpr int oBl = oBh + BN * BKP;
    constexpr int SH = (SPLIT ? 2 : 1) * (BM + BN) * BKP;  // halves per stage
    static_assert(NSTG * SH * 2 <= 49152, "must fit default 48KB smem");

    extern __shared__ __align__(16) __half sm[];
    const uint32_t smem_u32 = (uint32_t)__cvta_generic_to_shared(sm);

    const int tid = threadIdx.x, wid = tid >> 5, lane = tid & 31;
    const int wm = wid % WM, wn = wid / WM;
    const int qr = lane >> 2, qc = lane & 3;
    const int bm0 = blockIdx.x * BM, bn0 = blockIdx.y * BN;
    const int e = bn0 >> e_shift;
    const int nloc0 = bn0 - (e << e_shift);
    const __half* __restrict__ ApH = Ah_ + (size_t)bm0 * lda;
    const __half* __restrict__ ApL = SPLIT ? (Al_ + (size_t)bm0 * lda) : Ah_;
    const __half* __restrict__ BpH = Bh_ + (size_t)e * e_stride + (size_t)nloc0 * ldb;
    const __half* __restrict__ BpL = SPLIT ? (Bl_ + (size_t)e * e_stride + (size_t)nloc0 * ldb) : Bh_;

    // per-lane ldmatrix addressing (halves)
    const int a_row = wm * WTM + (lane & 15);
    const int a_col = (lane & 16) ? 8 : 0;
    const int b_row = wn * WTN + (lane & 7) + ((lane & 16) ? 8 : 0);
    const int b_col = (lane & 8) ? 8 : 0;

    float acc1[MT][NT][4], acc2[MT][NT][4];
    float accM[DRAIN ? MT : 1][DRAIN ? NT : 1][4];
    #pragma unroll
    for (int i = 0; i < MT; i++)
        #pragma unroll
        for (int j = 0; j < NT; j++)
            #pragma unroll
            for (int r = 0; r < 4; r++) { acc1[i][j][r] = 0.f; acc2[i][j][r] = 0.f; }
    if constexpr (DRAIN) {
        #pragma unroll
        for (int i = 0; i < MT; i++)
            #pragma unroll
            for (int j = 0; j < NT; j++)
                #pragma unroll
                for (int r = 0; r < 4; r++) accM[i][j][r] = 0.f;
    }

    auto load_stage = [&](int kt, int st) {
        const int k0 = kt * BK;
        __half* base = sm + st * SH;
        constexpr int CPR = BK / 8;      // 16B chunks per row
        constexpr int AQ = BM * CPR;
        #pragma unroll
        for (int it = 0; it < (AQ + 255) / 256; ++it) {
            int idx = tid + it * 256;
            if (AQ % 256 == 0 || idx < AQ) {
                int r = idx / CPR, c = idx % CPR;
                int doff = r * BKP + c * 8;
                size_t s = (size_t)r * lda + k0 + c * 8;
                cp16(base + doff, ApH + s);
                if constexpr (SPLIT) cp16(base + oAl + doff, ApL + s);
            }
        }
        constexpr int BQ = BN * CPR;
        #pragma unroll
        for (int it = 0; it < (BQ + 255) / 256; ++it) {
            int idx = tid + it * 256;
            if (BQ % 256 == 0 || idx < BQ) {
                int r = idx / CPR, c = idx % CPR;
                int doff = r * BKP + c * 8;
                size_t s = (size_t)r * ldb + k0 + c * 8;
                cp16(base + oBh + doff, BpH + s);
                if constexpr (SPLIT) cp16(base + oBl + doff, BpL + s);
            }
        }
        cp_commit();
    };

    const int KT = K / BK;
    // prologue: fill NSTG-1 stages (pad with empty groups if KT is small)
    #pragma unroll 1
    for (int s = 0; s < NSTG - 1; ++s) {
        if (s < KT) load_stage(s, s);
        else        cp_commit();
    }
    for (int kt = 0; kt < KT; ++kt) {
        // issue stage kt+NSTG-1 (or empty group) — pending-group count stays fixed
        if (kt + NSTG - 1 < KT) load_stage(kt + NSTG - 1, (kt + NSTG - 1) % NSTG);
        else                    cp_commit();
        cp_wait<NSTG - 2>();   // group kt (and older) complete
        __syncthreads();
        const uint32_t stage_u32 = smem_u32 + (uint32_t)((kt % NSTG) * SH) * 2u;
        #pragma unroll
        for (int kk = 0; kk < BK; kk += 16) {
            uint32_t ah[MT][4], al[MT][4], bh[NT][2], bl[NT][2];
            #pragma unroll
            for (int mt = 0; mt < MT; ++mt) {
                uint32_t off = stage_u32 + 2u * (uint32_t)((a_row + mt * 16) * BKP + kk + a_col);
                ldsm_x4(ah[mt][0], ah[mt][1], ah[mt][2], ah[mt][3], off);
                if constexpr (SPLIT)
                    ldsm_x4(al[mt][0], al[mt][1], al[mt][2], al[mt][3], off + 2u * oAl);
            }
            #pragma unroll
            for (int j = 0; j < NT / 2; ++j) {
                uint32_t off = stage_u32 + 2u * (uint32_t)(oBh + (b_row + j * 16) * BKP + kk + b_col);
                ldsm_x4(bh[2 * j][0], bh[2 * j][1], bh[2 * j + 1][0], bh[2 * j + 1][1], off);
                if constexpr (SPLIT)
                    ldsm_x4(bl[2 * j][0], bl[2 * j][1], bl[2 * j + 1][0], bl[2 * j + 1][1],
                            off + 2u * (uint32_t)(oBl - oBh));
            }
            #pragma unroll
            for (int mt = 0; mt < MT; ++mt)
                #pragma unroll
                for (int nt = 0; nt < NT; ++nt) {
                    mma_f16(acc1[mt][nt], ah[mt], bh[nt]);
                    if constexpr (SPLIT) {
                        mma_f16(acc2[mt][nt], ah[mt], bl[nt]);
                        mma_f16(acc2[mt][nt], al[mt], bh[nt]);
                    }
                }
        }
        if constexpr (DRAIN) {
            if ((kt & 63) == 63) {
                #pragma unroll
                for (int i = 0; i < MT; i++)
                    #pragma unroll
                    for (int j = 0; j < NT; j++)
                        #pragma unroll
                        for (int r = 0; r < 4; r++) {
                            accM[i][j][r] += acc1[i][j][r] + (SPLIT ? acc2[i][j][r] * RINV : 0.f);
                            acc1[i][j][r] = 0.f; acc2[i][j][r] = 0.f;
                        }
            }
        }
        __syncthreads();   // stage kt%NSTG free for overwrite next iteration
    }

    #pragma unroll
    for (int mt = 0; mt < MT; ++mt)
        #pragma unroll
        for (int nt = 0; nt < NT; ++nt) {
            float f[4];
            #pragma unroll
            for (int i = 0; i < 4; i++) {
                if constexpr (DRAIN)
                    f[i] = accM[mt][nt][i] + acc1[mt][nt][i] + (SPLIT ? acc2[mt][nt][i] * RINV : 0.f);
                else if constexpr (SPLIT)
                    f[i] = acc1[mt][nt][i] + acc2[mt][nt][i] * RINV;
                else
                    f[i] = acc1[mt][nt][i];
            }
            int row = bm0 + wm * WTM + mt * 16 + qr;
            int col = bn0 + wn * WTN + nt * 8 + qc * 2;
            epi(row, col, f[0], f[1]);
            epi(row + 8, col, f[2], f[3]);
        }
}

// ---------------- prep kernels --------------------------------------------------
__global__ void w1_tsplit_f16(const float* __restrict__ w1) {  // [e][d][h] -> [e][h][d] hi/lo
    __shared__ float t[32][33];
    int e = blockIdx.z, d0 = blockIdx.x * 32, h0 = blockIdx.y * 32;
    const float* src = w1 + ((size_t)e * DIN + d0) * DH + h0;
    for (int dy = threadIdx.y; dy < 32; dy += 8)
        t[dy][threadIdx.x] = src[(size_t)dy * DH + threadIdx.x];
    __syncthreads();
    __half* dh = g_W1th + ((size_t)e * DH + h0) * DIN + d0;
    __half* dl = g_W1tl + ((size_t)e * DH + h0) * DIN + d0;
    for (int hy = threadIdx.y; hy < 32; hy += 8) {
        __half hh, hl;
        split16(t[threadIdx.x][hy], hh, hl);
        dh[(size_t)hy * DIN + threadIdx.x] = hh;
        dl[(size_t)hy * DIN + threadIdx.x] = hl;
    }
}
// merged prep for W2 (hi/lo), W3 (single), W4 (single, padded)
__global__ void wmisc_f16(const float* __restrict__ w2, const float* __restrict__ w3,
                          const float* __restrict__ w4) {
    const int N2 = DMID * KH;
    const int N3 = NE * DH * DMID;
    const int N4 = DOUT * KH;
    int i = blockIdx.x * blockDim.x + threadIdx.x;
    if (i < N2) {
        int n = i / KH, k = i % KH;
        __half h, l;
        split16(w2[(size_t)k * DMID + n], h, l);
        g_W2th[i] = h; g_W2tl[i] = l;
    }
    if (i < N3) {
        int d = i % DMID, eh = i / DMID;
        int e = eh >> 10, h = eh & 1023;
        g_W3t[i] = __float2half_rn(w3[((size_t)e * DMID + d) * DH + h]);
    }
    if (i < N4) {
        int n = i / KH, k = i % KH;
        int e = k >> 10, h = k & 1023;
        g_W4t[i] = __float2half_rn(w4[((size_t)e * DH + h) * DOUT + n]);
    }
}
__global__ void concat_split_f16(const float* __restrict__ x8, const float* __restrict__ x16,
                                 const float* __restrict__ x32) {
    const int total = NB * DIN;
    for (int i = blockIdx.x * blockDim.x + threadIdx.x; i < total; i += gridDim.x * blockDim.x) {
        int b = i / DIN, j = i % DIN;
        float v = (j < 64) ? x8[b * 64 + j]
                : (j < 320) ? x16[b * 256 + (j - 64)]
                            : x32[b * 1024 + (j - 320)];
        __half h, l;
        split16(v, h, l);
        g_Xh[i] = h; g_Xl[i] = l;
    }
}

// ---------------- routing / aux -------------------------------------------------
__global__ void gate1_kernel(const float* __restrict__ gw, const float* __restrict__ gb) {
    int row = blockIdx.x * 8 + (threadIdx.x >> 5), lane = threadIdx.x & 31;
    if (row >= NB) return;
    float acc[NE];
    #pragma unroll
    for (int e = 0; e < NE; e++) acc[e] = 0.f;
    const __half* xh = g_Xh + (size_t)row * DIN;
    const __half* xl = g_Xl + (size_t)row * DIN;
    for (int d = lane; d < DIN; d += 32) {
        float xv = __half2float(xh[d]) + __half2float(xl[d]) * RINV;
        const float4* w4 = (const float4*)(gw + d * NE);
        float4 w0 = w4[0], w1 = w4[1];
        acc[0] += xv * w0.x; acc[1] += xv * w0.y; acc[2] += xv * w0.z; acc[3] += xv * w0.w;
        acc[4] += xv * w1.x; acc[5] += xv * w1.y; acc[6] += xv * w1.z; acc[7] += xv * w1.w;
    }
    #pragma unroll
    for (int o = 16; o; o >>= 1)
        #pragma unroll
        for (int e = 0; e < NE; e++) acc[e] += __shfl_xor_sync(0xffffffffu, acc[e], o);
    if (lane == 0) {
        float mx = -1e30f;
        #pragma unroll
        for (int e = 0; e < NE; e++) { acc[e] += gb[e]; mx = fmaxf(mx, acc[e]); }
        float s = 0.f;
        #pragma unroll
        for (int e = 0; e < NE; e++) { acc[e] = expf(acc[e] - mx); s += acc[e]; }
        float inv = 1.f / s;
        #pragma unroll
        for (int e = 0; e < NE; e++) g_P1[row * NE + e] = acc[e] * inv;
    }
}
__global__ void gate2_kernel(const float* __restrict__ gw) {
    int row = blockIdx.x * 8 + (threadIdx.x >> 5), lane = threadIdx.x & 31;
    if (row >= NB) return;
    float acc[NE];
    #pragma unroll
    for (int e = 0; e < NE; e++) acc[e] = 0.f;
    const float* y = g_Y + (size_t)row * DMID;
    #pragma unroll
    for (int it = 0; it < DMID / 32; it++) {
        int o = lane + it * 32;
        float yv = y[o];
        const float4* w4 = (const float4*)(gw + o * NE);
        float4 w0 = w4[0], w1 = w4[1];
        acc[0] += yv * w0.x; acc[1] += yv * w0.y; acc[2] += yv * w0.z; acc[3] += yv * w0.w;
        acc[4] += yv * w1.x; acc[5] += yv * w1.y; acc[6] += yv * w1.z; acc[7] += yv * w1.w;
    }
    #pragma unroll
    for (int o = 16; o; o >>= 1)
        #pragma unroll
        for (int e = 0; e < NE; e++) acc[e] += __shfl_xor_sync(0xffffffffu, acc[e], o);
    if (lane == 0) {
        float mx = -1e30f;
        #pragma unroll
        for (int e = 0; e < NE; e++) mx = fmaxf(mx, acc[e]);
        float s = 0.f;
        #pragma unroll
        for (int e = 0; e < NE; e++) { acc[e] = expf(acc[e] - mx); s += acc[e]; }
        float inv = 1.f / s;
        #pragma unroll
        for (int e = 0; e < NE; e++) { acc[e] *= inv; g_probs2[row * NE + e] = acc[e]; }
        int i1 = 0;
        #pragma unroll
        for (int e = 1; e < NE; e++) if (acc[e] > acc[i1]) i1 = e;
        int i2 = (i1 == 0) ? 1 : 0;
        #pragma unroll
        for (int e = 0; e < NE; e++) if (e != i1 && acc[e] > acc[i2]) i2 = e;
        float r = 1.f / (acc[i1] + acc[i2] + 1e-6f);
        #pragma unroll
        for (int e = 0; e < NE; e++)
            g_coef[row * NE + e] = (e == i1) ? acc[i1] * r : ((e == i2) ? acc[i2] * r : 0.f);
    }
}
__global__ void aux_kernel(float* __restrict__ out) {
    __shared__ float s_sum[256], s_cnt[256];
    int t = threadIdx.x, e = t & 7, chunk = t >> 3;
    float sum = 0.f, cnt = 0.f;
    for (int b = chunk; b < NB; b += 32) {
        sum += g_probs2[b * NE + e];
        cnt += (g_coef[b * NE + e] > 0.f) ? 1.f : 0.f;
    }
    s_sum[t] = sum; s_cnt[t] = cnt;
    __syncthreads();
    for (int s = 128; s >= 8; s >>= 1) {
        if (t < s) { s_sum[t] += s_sum[t + s]; s_cnt[t] += s_cnt[t + s]; }
        __syncthreads();
    }
    if (t == 0) {
        float aux = 0.f;
        #pragma unroll
        for (int ee = 0; ee < NE; ee++)
            aux += (s_sum[ee] / (float)NB) * (s_cnt[ee] / (float)(NB * 2));
        out[(size_t)NB * DOUT] = (float)NE * aux;
    }
}

// ---------------- launch --------------------------------------------------------
extern "C" void kernel_launch(void* const* d_in, const int* in_sizes, int n_in,
                              void* d_out, int out_size) {
    const float* x8   = (const float*)d_in[0];
    const float* x16  = (const float*)d_in[1];
    const float* x32  = (const float*)d_in[2];
    const float* g1w  = (const float*)d_in[3];
    const float* g1b  = (const float*)d_in[4];
    const float* e1w1 = (const float*)d_in[5];
    const float* e1b1 = (const float*)d_in[6];
    const float* e1w2 = (const float*)d_in[7];
    const float* e1b2 = (const float*)d_in[8];
    const float* g2w  = (const float*)d_in[9];
    const float* e2w1 = (const float*)d_in[10];
    const float* e2b1 = (const float*)d_in[11];
    const float* e2w2 = (const float*)d_in[12];
    const float* e2b2 = (const float*)d_in[13];
    float* out = (float*)d_out;

    __half *Xh, *Xl, *W1h, *W1l, *W2h, *W2l, *W3, *W4, *Hh, *Hl, *Yh;
    cudaGetSymbolAddress((void**)&Xh,  g_Xh);
    cudaGetSymbolAddress((void**)&Xl,  g_Xl);
    cudaGetSymbolAddress((void**)&W1h, g_W1th);
    cudaGetSymbolAddress((void**)&W1l, g_W1tl);
    cudaGetSymbolAddress((void**)&W2h, g_W2th);
    cudaGetSymbolAddress((void**)&W2l, g_W2tl);
    cudaGetSymbolAddress((void**)&W3,  g_W3t);
    cudaGetSymbolAddress((void**)&W4,  g_W4t);
    cudaGetSymbolAddress((void**)&Hh,  g_Hh);
    cudaGetSymbolAddress((void**)&Hl,  g_Hl);
    cudaGetSymbolAddress((void**)&Yh,  g_Yh);

    // prep needed by GEMM1 first; GEMM1 early for ncu capture window
    w1_tsplit_f16<<<dim3(DIN / 32, DH / 32, NE), dim3(32, 8)>>>(e1w1);       // 0
    concat_split_f16<<<1024, 256>>>(x8, x16, x32);                           // 1
    gate1_kernel<<<NB / 8, 256>>>(g1w, g1b);                                 // 2

    // layer1 GEMM1 (fp16x3, 4-stage, 64x64xBK16): smem 49152 (= default limit)
    gemm_f16k<64, 64, 16, 2, 4, true, false, Epi1><<<dim3(NB / 64, KH / 64), 256, 49152>>>(
        Xh, Xl, DIN, W1h, W1l, DIN, (size_t)DH * DIN, 10, DIN, Epi1{e1b1});  // 3

    wmisc_f16<<<(DOUT * KH + 255) / 256, 256>>>(e1w2, e2w1, e2w2);           // 4

    // layer1 GEMM2 (fp16x3 + drain, 4-stage, 64x64xBK16): smem 49152
    gemm_f16k<64, 64, 16, 2, 4, true, true, Epi2><<<dim3(NB / 64, DMID / 64), 256, 49152>>>(
        Hh, Hl, KH, W2h, W2l, KH, 0, 30, KH, Epi2{e1b2});                    // 5

    gate2_kernel<<<NB / 8, 256>>>(g2w);                                      // 6

    // layer2 GEMM1 (fp16 single, 4-stage, 128x64xBK16): smem 36864
    gemm_f16k<128, 64, 16, 4, 2, false, false, Epi3><<<dim3(NB / 128, KH / 64), 256, 36864>>>(
        Yh, Yh, DMID, W3, W3, DMID, (size_t)DH * DMID, 10, DMID, Epi3{e2b1});

    // layer2 GEMM2 (fp16 single, 4-stage, 64x64xBK16): smem 24576
    gemm_f16k<64, 64, 16, 2, 4, false, false, Epi4><<<dim3(NB / 64, DOUTP / 64), 256, 24576>>>(
        Hh, Hh, KH, W4, W4, KH, 0, 30, KH, Epi4{e2b2, out});

    aux_kernel<<<1, 256>>>(out);
}

// round 15
// speedup vs baseline: 1.3487x; 1.3487x over previous
#include <cuda_runtime.h>
#include <cuda_fp16.h>
#include <cstdint>

#define NB 8192
#define NE 8
#define DIN 1344
#define DH 1024
#define KH (NE * DH)   // 8192
#define DMID 128
#define DOUT 162
#define DOUTP 192      // DOUT padded to tile multiple (rows 162..191 stay zero)
#define RSCL 2048.0f
#define RINV (1.0f / 2048.0f)

// ---------------- device scratch (static; ~362 MB, all zero-initialized) --------
__device__ __align__(256) __half g_Xh [NB * DIN];
__device__ __align__(256) __half g_Xl [NB * DIN];
__device__ __align__(256) __half g_W1th[NE * DH * DIN];   // [e][h][d] hi
__device__ __align__(256) __half g_W1tl[NE * DH * DIN];   // residual*2^11
__device__ __align__(256) __half g_W2th[DMID * KH];       // [n][k]
__device__ __align__(256) __half g_W2tl[DMID * KH];
__device__ __align__(256) __half g_W3t [NE * DH * DMID];  // [e][h][dmid] single
__device__ __align__(256) __half g_W4t [DOUTP * KH];      // [n][k] single, zero-padded rows
__device__ __align__(256) __half g_Hh [(size_t)NB * KH];  // hidden hi (both layers)
__device__ __align__(256) __half g_Hl [(size_t)NB * KH];  // hidden residual*2^11 (layer1)
__device__ __align__(256) float  g_Y  [NB * DMID];        // fp32 y (router input)
__device__ __align__(256) __half g_Yh [NB * DMID];        // half y (GEMM3 A)
__device__ float g_P1[NB * NE];
__device__ float g_coef[NB * NE];
__device__ float g_probs2[NB * NE];

// ---------------- helpers ------------------------------------------------------
__device__ __forceinline__ float gelu_f(float x) {
    return 0.5f * x * (1.0f + erff(x * 0.70710678118654752f));
}
__device__ __forceinline__ void split16(float v, __half& h, __half& l) {
    h = __float2half_rn(v);
    l = __float2half_rn((v - __half2float(h)) * RSCL);
}
__device__ __forceinline__ void cp16(void* smem, const void* gmem) {
    uint32_t s = (uint32_t)__cvta_generic_to_shared(smem);
    asm volatile("cp.async.cg.shared.global [%0], [%1], 16;\n" :: "r"(s), "l"(gmem));
}
__device__ __forceinline__ void cp_commit() { asm volatile("cp.async.commit_group;\n"); }
template <int N>
__device__ __forceinline__ void cp_wait() { asm volatile("cp.async.wait_group %0;\n" :: "n"(N)); }

__device__ __forceinline__ void mma_f16(float* c, const uint32_t* a, const uint32_t* b) {
    asm volatile("mma.sync.aligned.m16n8k16.row.col.f32.f16.f16.f32 "
        "{%0,%1,%2,%3}, {%4,%5,%6,%7}, {%8,%9}, {%0,%1,%2,%3};\n"
        : "+f"(c[0]), "+f"(c[1]), "+f"(c[2]), "+f"(c[3])
        : "r"(a[0]), "r"(a[1]), "r"(a[2]), "r"(a[3]), "r"(b[0]), "r"(b[1]));
}
__device__ __forceinline__ void ldsm_x4(uint32_t& r0, uint32_t& r1, uint32_t& r2, uint32_t& r3,
                                        uint32_t addr) {
    asm volatile("ldmatrix.sync.aligned.m8n8.x4.shared.b16 {%0,%1,%2,%3}, [%4];"
        : "=r"(r0), "=r"(r1), "=r"(r2), "=r"(r3) : "r"(addr));
}
// swizzled segment offset (halves): row r, 8-half chunk c (BK=16 -> c in {0,1})
__device__ __forceinline__ int swz16(int r, int c) {
    return r * 16 + ((c ^ ((r >> 2) & 1)) << 3);
}

// ---------------- epilogue functors (pairwise: cols n, n+1) --------------------
struct Epi1 {  // layer1 GEMM1: h1s = probs1 * gelu(v + b1) -> split half pair
    const float* b1;
    __device__ void operator()(int m, int n, float v0, float v1) const {
        int e = n >> 10, h = n & 1023;
        float p = g_P1[m * NE + e];
        float w0 = gelu_f(v0 + b1[e * DH + h]) * p;
        float w1 = gelu_f(v1 + b1[e * DH + h + 1]) * p;
        __half h0, l0, h1, l1;
        split16(w0, h0, l0); split16(w1, h1, l1);
        *(__half2*)(g_Hh + (size_t)m * KH + n) = __halves2half2(h0, h1);
        *(__half2*)(g_Hl + (size_t)m * KH + n) = __halves2half2(l0, l1);
    }
};
struct Epi2 {  // layer1 GEMM2: y = gelu(v + sum_e p*b2) -> fp32 + half
    const float* b2;
    __device__ void operator()(int m, int n, float v0, float v1) const {
        float ba = 0.f, bb = 0.f;
        #pragma unroll
        for (int e = 0; e < NE; e++) {
            float p = g_P1[m * NE + e];
            ba += p * b2[e * DMID + n];
            bb += p * b2[e * DMID + n + 1];
        }
        float y0 = gelu_f(v0 + ba), y1 = gelu_f(v1 + bb);
        g_Y[m * DMID + n] = y0;
        g_Y[m * DMID + n + 1] = y1;
        *(__half2*)(g_Yh + m * DMID + n) =
            __halves2half2(__float2half_rn(y0), __float2half_rn(y1));
    }
};
struct Epi3 {  // layer2 GEMM1: h2s = coef * gelu(v + b1) -> single half
    const float* b1;
    __device__ void operator()(int m, int n, float v0, float v1) const {
        int e = n >> 10, h = n & 1023;
        float c = g_coef[m * NE + e];
        float w0 = gelu_f(v0 + b1[e * DH + h]) * c;
        float w1 = gelu_f(v1 + b1[e * DH + h + 1]) * c;
        *(__half2*)(g_Hh + (size_t)m * KH + n) =
            __halves2half2(__float2half_rn(w0), __float2half_rn(w1));
    }
};
struct Epi4 {  // layer2 GEMM2: out = v + sum_e coef*b2 (only n < DOUT written)
    const float* b2;
    float* out;
    __device__ void operator()(int m, int n, float v0, float v1) const {
        #pragma unroll
        for (int t = 0; t < 2; t++) {
            int nn = n + t;
            float vv = t ? v1 : v0;
            if (nn < DOUT) {
                float bias = 0.f;
                #pragma unroll
                for (int e = 0; e < NE; e++) bias += g_coef[m * NE + e] * b2[e * DOUT + nn];
                out[(size_t)m * DOUT + nn] = vv + bias;
            }
        }
    }
};

// ---------------- fp16 tensor-core GEMM (single or scaled-residual x3) ---------
// C[m,n] = sum_k A[m,k]*B[n,k] (B stored n-major [n][k], N padded to tile mult).
// SPLIT: acc1 += Ah*Bh ; acc2 += Ah*Bl + Al*Bh ; final = acc1 + acc2*2^-11.
// BK=16, XOR-swizzled smem (no padding). NSTG-stage cp.async pipeline; all
// dynamic smem < 48KB default (no attribute calls). Empty commit groups keep
// the pending-group count invariant through prologue and tail.
template <int BM, int BN, int BK, int WM, int WN, int NSTG, bool SPLIT, bool DRAIN, class Epi>
__global__ void __launch_bounds__(256) gemm_f16k(
    const __half* __restrict__ Ah_, const __half* __restrict__ Al_, int lda,
    const __half* __restrict__ Bh_, const __half* __restrict__ Bl_, int ldb,
    size_t e_stride, int e_shift, int K, Epi epi)
{
    static_assert(BK == 16, "swizzle hardcoded for BK=16");
    constexpr int WTM = BM / WM, WTN = BN / WN;
    constexpr int MT = WTM / 16, NT = WTN / 8;
    static_assert(NT % 2 == 0, "B ldmatrix pairs two n-tiles");
    constexpr int oAl = BM * BK;
    constexpr int oBh = (SPLIT ? 2 : 1) * BM * BK;
    constexpr int oBl = oBh + BN * BK;
    constexpr int SH = (SPLIT ? 2 : 1) * (BM + BN) * BK;   // halves per stage
    static_assert(NSTG * SH * 2 < 49152, "must fit under default 48KB smem");

    extern __shared__ __align__(16) __half sm[];
    const uint32_t smem_u32 = (uint32_t)__cvta_generic_to_shared(sm);

    const int tid = threadIdx.x, wid = tid >> 5, lane = tid & 31;
    const int wm = wid % WM, wn = wid / WM;
    const int qr = lane >> 2, qc = lane & 3;
    const int bm0 = blockIdx.x * BM, bn0 = blockIdx.y * BN;
    const int e = bn0 >> e_shift;
    const int nloc0 = bn0 - (e << e_shift);
    const __half* __restrict__ ApH = Ah_ + (size_t)bm0 * lda;
    const __half* __restrict__ ApL = SPLIT ? (Al_ + (size_t)bm0 * lda) : Ah_;
    const __half* __restrict__ BpH = Bh_ + (size_t)e * e_stride + (size_t)nloc0 * ldb;
    const __half* __restrict__ BpL = SPLIT ? (Bl_ + (size_t)e * e_stride + (size_t)nloc0 * ldb) : Bh_;

    // per-lane ldmatrix addressing
    const int a_row = wm * WTM + (lane & 15);
    const int a_chk = (lane & 16) ? 1 : 0;
    const int b_row = wn * WTN + (lane & 7) + ((lane & 16) ? 8 : 0);
    const int b_chk = (lane & 8) ? 1 : 0;

    float acc1[MT][NT][4], acc2[MT][NT][4];
    float accM[DRAIN ? MT : 1][DRAIN ? NT : 1][4];
    #pragma unroll
    for (int i = 0; i < MT; i++)
        #pragma unroll
        for (int j = 0; j < NT; j++)
            #pragma unroll
            for (int r = 0; r < 4; r++) { acc1[i][j][r] = 0.f; acc2[i][j][r] = 0.f; }
    if constexpr (DRAIN) {
        #pragma unroll
        for (int i = 0; i < MT; i++)
            #pragma unroll
            for (int j = 0; j < NT; j++)
                #pragma unroll
                for (int r = 0; r < 4; r++) accM[i][j][r] = 0.f;
    }

    auto load_stage = [&](int kt, int st) {
        const int k0 = kt * BK;
        __half* base = sm + st * SH;
        constexpr int AQ = BM * 2;       // 2 chunks of 8 halves per row
        #pragma unroll
        for (int it = 0; it < (AQ + 255) / 256; ++it) {
            int idx = tid + it * 256;
            if (AQ % 256 == 0 || idx < AQ) {
                int r = idx >> 1, c = idx & 1;
                int doff = swz16(r, c);
                size_t s = (size_t)r * lda + k0 + c * 8;
                cp16(base + doff, ApH + s);
                if constexpr (SPLIT) cp16(base + oAl + doff, ApL + s);
            }
        }
        constexpr int BQ = BN * 2;
        #pragma unroll
        for (int it = 0; it < (BQ + 255) / 256; ++it) {
            int idx = tid + it * 256;
            if (BQ % 256 == 0 || idx < BQ) {
                int r = idx >> 1, c = idx & 1;
                int doff = swz16(r, c);
                size_t s = (size_t)r * ldb + k0 + c * 8;
                cp16(base + oBh + doff, BpH + s);
                if constexpr (SPLIT) cp16(base + oBl + doff, BpL + s);
            }
        }
        cp_commit();
    };

    const int KT = K / BK;
    // prologue: fill NSTG-1 stages (pad with empty groups if KT is small)
    #pragma unroll 1
    for (int s = 0; s < NSTG - 1; ++s) {
        if (s < KT) load_stage(s, s);
        else        cp_commit();
    }
    for (int kt = 0; kt < KT; ++kt) {
        if (kt + NSTG - 1 < KT) load_stage(kt + NSTG - 1, (kt + NSTG - 1) % NSTG);
        else                    cp_commit();
        cp_wait<NSTG - 2>();
        __syncthreads();
        const uint32_t stage_u32 = smem_u32 + (uint32_t)((kt % NSTG) * SH) * 2u;
        {
            uint32_t ah[MT][4], al[MT][4], bh[NT][2], bl[NT][2];
            #pragma unroll
            for (int mt = 0; mt < MT; ++mt) {
                int r = a_row + mt * 16;
                uint32_t off = stage_u32 + 2u * (uint32_t)swz16(r, a_chk);
                ldsm_x4(ah[mt][0], ah[mt][1], ah[mt][2], ah[mt][3], off);
                if constexpr (SPLIT)
                    ldsm_x4(al[mt][0], al[mt][1], al[mt][2], al[mt][3], off + 2u * oAl);
            }
            #pragma unroll
            for (int j = 0; j < NT / 2; ++j) {
                int r = b_row + j * 16;
                uint32_t off = stage_u32 + 2u * (uint32_t)(oBh + swz16(r, b_chk));
                ldsm_x4(bh[2 * j][0], bh[2 * j][1], bh[2 * j + 1][0], bh[2 * j + 1][1], off);
                if constexpr (SPLIT)
                    ldsm_x4(bl[2 * j][0], bl[2 * j][1], bl[2 * j + 1][0], bl[2 * j + 1][1],
                            off + 2u * (uint32_t)(oBl - oBh));
            }
            #pragma unroll
            for (int mt = 0; mt < MT; ++mt)
                #pragma unroll
                for (int nt = 0; nt < NT; ++nt) {
                    mma_f16(acc1[mt][nt], ah[mt], bh[nt]);
                    if constexpr (SPLIT) {
                        mma_f16(acc2[mt][nt], ah[mt], bl[nt]);
                        mma_f16(acc2[mt][nt], al[mt], bh[nt]);
                    }
                }
        }
        if constexpr (DRAIN) {
            if ((kt & 63) == 63) {
                #pragma unroll
                for (int i = 0; i < MT; i++)
                    #pragma unroll
                    for (int j = 0; j < NT; j++)
                        #pragma unroll
                        for (int r = 0; r < 4; r++) {
                            accM[i][j][r] += acc1[i][j][r] + (SPLIT ? acc2[i][j][r] * RINV : 0.f);
                            acc1[i][j][r] = 0.f; acc2[i][j][r] = 0.f;
                        }
            }
        }
        __syncthreads();
    }

    #pragma unroll
    for (int mt = 0; mt < MT; ++mt)
        #pragma unroll
        for (int nt = 0; nt < NT; ++nt) {
            float f[4];
            #pragma unroll
            for (int i = 0; i < 4; i++) {
                if constexpr (DRAIN)
                    f[i] = accM[mt][nt][i] + acc1[mt][nt][i] + (SPLIT ? acc2[mt][nt][i] * RINV : 0.f);
                else if constexpr (SPLIT)
                    f[i] = acc1[mt][nt][i] + acc2[mt][nt][i] * RINV;
                else
                    f[i] = acc1[mt][nt][i];
            }
            int row = bm0 + wm * WTM + mt * 16 + qr;
            int col = bn0 + wn * WTN + nt * 8 + qc * 2;
            epi(row, col, f[0], f[1]);
            epi(row + 8, col, f[2], f[3]);
        }
}

// ---------------- prep kernels --------------------------------------------------
__global__ void w1_tsplit_f16(const float* __restrict__ w1) {  // [e][d][h] -> [e][h][d] hi/lo
    __shared__ float t[32][33];
    int e = blockIdx.z, d0 = blockIdx.x * 32, h0 = blockIdx.y * 32;
    const float* src = w1 + ((size_t)e * DIN + d0) * DH + h0;
    for (int dy = threadIdx.y; dy < 32; dy += 8)
        t[dy][threadIdx.x] = src[(size_t)dy * DH + threadIdx.x];
    __syncthreads();
    __half* dh = g_W1th + ((size_t)e * DH + h0) * DIN + d0;
    __half* dl = g_W1tl + ((size_t)e * DH + h0) * DIN + d0;
    for (int hy = threadIdx.y; hy < 32; hy += 8) {
        __half hh, hl;
        split16(t[threadIdx.x][hy], hh, hl);
        dh[(size_t)hy * DIN + threadIdx.x] = hh;
        dl[(size_t)hy * DIN + threadIdx.x] = hl;
    }
}
// merged prep for W2 (hi/lo), W3 (single), W4 (single, padded)
__global__ void wmisc_f16(const float* __restrict__ w2, const float* __restrict__ w3,
                          const float* __restrict__ w4) {
    const int N2 = DMID * KH;
    const int N3 = NE * DH * DMID;
    const int N4 = DOUT * KH;
    int i = blockIdx.x * blockDim.x + threadIdx.x;
    if (i < N2) {
        int n = i / KH, k = i % KH;
        __half h, l;
        split16(w2[(size_t)k * DMID + n], h, l);
        g_W2th[i] = h; g_W2tl[i] = l;
    }
    if (i < N3) {
        int d = i % DMID, eh = i / DMID;
        int e = eh >> 10, h = eh & 1023;
        g_W3t[i] = __float2half_rn(w3[((size_t)e * DMID + d) * DH + h]);
    }
    if (i < N4) {
        int n = i / KH, k = i % KH;
        int e = k >> 10, h = k & 1023;
        g_W4t[i] = __float2half_rn(w4[((size_t)e * DH + h) * DOUT + n]);
    }
}
__global__ void concat_split_f16(const float* __restrict__ x8, const float* __restrict__ x16,
                                 const float* __restrict__ x32) {
    const int total = NB * DIN;
    for (int i = blockIdx.x * blockDim.x + threadIdx.x; i < total; i += gridDim.x * blockDim.x) {
        int b = i / DIN, j = i % DIN;
        float v = (j < 64) ? x8[b * 64 + j]
                : (j < 320) ? x16[b * 256 + (j - 64)]
                            : x32[b * 1024 + (j - 320)];
        __half h, l;
        split16(v, h, l);
        g_Xh[i] = h; g_Xl[i] = l;
    }
}

// ---------------- routing / aux -------------------------------------------------
__global__ void gate1_kernel(const float* __restrict__ gw, const float* __restrict__ gb) {
    int row = blockIdx.x * 8 + (threadIdx.x >> 5), lane = threadIdx.x & 31;
    if (row >= NB) return;
    float acc[NE];
    #pragma unroll
    for (int e = 0; e < NE; e++) acc[e] = 0.f;
    const __half* xh = g_Xh + (size_t)row * DIN;
    const __half* xl = g_Xl + (size_t)row * DIN;
    for (int d = lane; d < DIN; d += 32) {
        float xv = __half2float(xh[d]) + __half2float(xl[d]) * RINV;
        const float4* w4 = (const float4*)(gw + d * NE);
        float4 w0 = w4[0], w1 = w4[1];
        acc[0] += xv * w0.x; acc[1] += xv * w0.y; acc[2] += xv * w0.z; acc[3] += xv * w0.w;
        acc[4] += xv * w1.x; acc[5] += xv * w1.y; acc[6] += xv * w1.z; acc[7] += xv * w1.w;
    }
    #pragma unroll
    for (int o = 16; o; o >>= 1)
        #pragma unroll
        for (int e = 0; e < NE; e++) acc[e] += __shfl_xor_sync(0xffffffffu, acc[e], o);
    if (lane == 0) {
        float mx = -1e30f;
        #pragma unroll
        for (int e = 0; e < NE; e++) { acc[e] += gb[e]; mx = fmaxf(mx, acc[e]); }
        float s = 0.f;
        #pragma unroll
        for (int e = 0; e < NE; e++) { acc[e] = expf(acc[e] - mx); s += acc[e]; }
        float inv = 1.f / s;
        #pragma unroll
        for (int e = 0; e < NE; e++) g_P1[row * NE + e] = acc[e] * inv;
    }
}
__global__ void gate2_kernel(const float* __restrict__ gw) {
    int row = blockIdx.x * 8 + (threadIdx.x >> 5), lane = threadIdx.x & 31;
    if (row >= NB) return;
    float acc[NE];
    #pragma unroll
    for (int e = 0; e < NE; e++) acc[e] = 0.f;
    const float* y = g_Y + (size_t)row * DMID;
    #pragma unroll
    for (int it = 0; it < DMID / 32; it++) {
        int o = lane + it * 32;
        float yv = y[o];
        const float4* w4 = (const float4*)(gw + o * NE);
        float4 w0 = w4[0], w1 = w4[1];
        acc[0] += yv * w0.x; acc[1] += yv * w0.y; acc[2] += yv * w0.z; acc[3] += yv * w0.w;
        acc[4] += yv * w1.x; acc[5] += yv * w1.y; acc[6] += yv * w1.z; acc[7] += yv * w1.w;
    }
    #pragma unroll
    for (int o = 16; o; o >>= 1)
        #pragma unroll
        for (int e = 0; e < NE; e++) acc[e] += __shfl_xor_sync(0xffffffffu, acc[e], o);
    if (lane == 0) {
        float mx = -1e30f;
        #pragma unroll
        for (int e = 0; e < NE; e++) mx = fmaxf(mx, acc[e]);
        float s = 0.f;
        #pragma unroll
        for (int e = 0; e < NE; e++) { acc[e] = expf(acc[e] - mx); s += acc[e]; }
        float inv = 1.f / s;
        #pragma unroll
        for (int e = 0; e < NE; e++) { acc[e] *= inv; g_probs2[row * NE + e] = acc[e]; }
        int i1 = 0;
        #pragma unroll
        for (int e = 1; e < NE; e++) if (acc[e] > acc[i1]) i1 = e;
        int i2 = (i1 == 0) ? 1 : 0;
        #pragma unroll
        for (int e = 0; e < NE; e++) if (e != i1 && acc[e] > acc[i2]) i2 = e;
        float r = 1.f / (acc[i1] + acc[i2] + 1e-6f);
        #pragma unroll
        for (int e = 0; e < NE; e++)
            g_coef[row * NE + e] = (e == i1) ? acc[i1] * r : ((e == i2) ? acc[i2] * r : 0.f);
    }
}
__global__ void aux_kernel(float* __restrict__ out) {
    __shared__ float s_sum[256], s_cnt[256];
    int t = threadIdx.x, e = t & 7, chunk = t >> 3;
    float sum = 0.f, cnt = 0.f;
    for (int b = chunk; b < NB; b += 32) {
        sum += g_probs2[b * NE + e];
        cnt += (g_coef[b * NE + e] > 0.f) ? 1.f : 0.f;
    }
    s_sum[t] = sum; s_cnt[t] = cnt;
    __syncthreads();
    for (int s = 128; s >= 8; s >>= 1) {
        if (t < s) { s_sum[t] += s_sum[t + s]; s_cnt[t] += s_cnt[t + s]; }
        __syncthreads();
    }
    if (t == 0) {
        float aux = 0.f;
        #pragma unroll
        for (int ee = 0; ee < NE; ee++)
            aux += (s_sum[ee] / (float)NB) * (s_cnt[ee] / (float)(NB * 2));
        out[(size_t)NB * DOUT] = (float)NE * aux;
    }
}

// ---------------- launch --------------------------------------------------------
extern "C" void kernel_launch(void* const* d_in, const int* in_sizes, int n_in,
                              void* d_out, int out_size) {
    const float* x8   = (const float*)d_in[0];
    const float* x16  = (const float*)d_in[1];
    const float* x32  = (const float*)d_in[2];
    const float* g1w  = (const float*)d_in[3];
    const float* g1b  = (const float*)d_in[4];
    const float* e1w1 = (const float*)d_in[5];
    const float* e1b1 = (const float*)d_in[6];
    const float* e1w2 = (const float*)d_in[7];
    const float* e1b2 = (const float*)d_in[8];
    const float* g2w  = (const float*)d_in[9];
    const float* e2w1 = (const float*)d_in[10];
    const float* e2b1 = (const float*)d_in[11];
    const float* e2w2 = (const float*)d_in[12];
    const float* e2b2 = (const float*)d_in[13];
    float* out = (float*)d_out;

    __half *Xh, *Xl, *W1h, *W1l, *W2h, *W2l, *W3, *W4, *Hh, *Hl, *Yh;
    cudaGetSymbolAddress((void**)&Xh,  g_Xh);
    cudaGetSymbolAddress((void**)&Xl,  g_Xl);
    cudaGetSymbolAddress((void**)&W1h, g_W1th);
    cudaGetSymbolAddress((void**)&W1l, g_W1tl);
    cudaGetSymbolAddress((void**)&W2h, g_W2th);
    cudaGetSymbolAddress((void**)&W2l, g_W2tl);
    cudaGetSymbolAddress((void**)&W3,  g_W3t);
    cudaGetSymbolAddress((void**)&W4,  g_W4t);
    cudaGetSymbolAddress((void**)&Hh,  g_Hh);
    cudaGetSymbolAddress((void**)&Hl,  g_Hl);
    cudaGetSymbolAddress((void**)&Yh,  g_Yh);

    // prep needed by GEMM1 first; GEMM1 early for ncu capture window
    w1_tsplit_f16<<<dim3(DIN / 32, DH / 32, NE), dim3(32, 8)>>>(e1w1);       // 0
    concat_split_f16<<<1024, 256>>>(x8, x16, x32);                           // 1
    gate1_kernel<<<NB / 8, 256>>>(g1w, g1b);                                 // 2

    // layer1 GEMM1 (fp16x3, 3-stage, 128x64 BK16, swizzled): smem 36864
    gemm_f16k<128, 64, 16, 4, 2, 3, true, false, Epi1><<<dim3(NB / 128, KH / 64), 256, 36864>>>(
        Xh, Xl, DIN, W1h, W1l, DIN, (size_t)DH * DIN, 10, DIN, Epi1{e1b1});  // 3

    wmisc_f16<<<(DOUT * KH + 255) / 256, 256>>>(e1w2, e2w1, e2w2);           // 4

    // layer1 GEMM2 (fp16x3 + drain, 4-stage, 64x64 BK16): smem 32768
    gemm_f16k<64, 64, 16, 2, 4, 4, true, true, Epi2><<<dim3(NB / 64, DMID / 64), 256, 32768>>>(
        Hh, Hl, KH, W2h, W2l, KH, 0, 30, KH, Epi2{e1b2});                    // 5

    gate2_kernel<<<NB / 8, 256>>>(g2w);                                      // 6

    // layer2 GEMM1 (fp16 single, 4-stage, 128x64 BK16): smem 24576
    gemm_f16k<128, 64, 16, 4, 2, 4, false, false, Epi3><<<dim3(NB / 128, KH / 64), 256, 24576>>>(
        Yh, Yh, DMID, W3, W3, DMID, (size_t)DH * DMID, 10, DMID, Epi3{e2b1});

    // layer2 GEMM2 (fp16 single, 4-stage, 64x64 BK16): smem 16384
    gemm_f16k<64, 64, 16, 2, 4, 4, false, false, Epi4><<<dim3(NB / 64, DOUTP / 64), 256, 16384>>>(
        Hh, Hh, KH, W4, W4, KH, 0, 30, KH, Epi4{e2b2, out});

    aux_kernel<<<1, 256>>>(out);
}

// round 16
// speedup vs baseline: 1.5242x; 1.1301x over previous
#include <cuda_runtime.h>
#include <cuda_fp16.h>
#include <cstdint>

#define NB 8192
#define NE 8
#define DIN 1344
#define DH 1024
#define KH (NE * DH)   // 8192
#define DMID 128
#define DOUT 162
#define DOUTP 192      // DOUT padded to tile multiple (rows 162..191 stay zero)
#define RSCL 2048.0f
#define RINV (1.0f / 2048.0f)

// ---------------- device scratch (static; ~362 MB, all zero-initialized) --------
__device__ __align__(256) __half g_Xh [NB * DIN];
__device__ __align__(256) __half g_Xl [NB * DIN];
__device__ __align__(256) __half g_W1th[NE * DH * DIN];   // [e][h][d] hi
__device__ __align__(256) __half g_W1tl[NE * DH * DIN];   // residual*2^11
__device__ __align__(256) __half g_W2th[DMID * KH];       // [n][k]
__device__ __align__(256) __half g_W2tl[DMID * KH];
__device__ __align__(256) __half g_W3t [NE * DH * DMID];  // [e][h][dmid] single
__device__ __align__(256) __half g_W4t [DOUTP * KH];      // [n][k] single, zero-padded rows
__device__ __align__(256) __half g_Hh [(size_t)NB * KH];  // hidden hi (both layers)
__device__ __align__(256) __half g_Hl [(size_t)NB * KH];  // hidden residual*2^11 (layer1)
__device__ __align__(256) float  g_Y  [NB * DMID];        // fp32 y (router input)
__device__ __align__(256) __half g_Yh [NB * DMID];        // half y (GEMM3 A)
__device__ float g_P1[NB * NE];
__device__ float g_coef[NB * NE];
__device__ float g_probs2[NB * NE];

// ---------------- helpers ------------------------------------------------------
__device__ __forceinline__ float gelu_f(float x) {
    return 0.5f * x * (1.0f + erff(x * 0.70710678118654752f));
}
__device__ __forceinline__ void split16(float v, __half& h, __half& l) {
    h = __float2half_rn(v);
    l = __float2half_rn((v - __half2float(h)) * RSCL);
}
__device__ __forceinline__ void cp16(void* smem, const void* gmem) {
    uint32_t s = (uint32_t)__cvta_generic_to_shared(smem);
    asm volatile("cp.async.cg.shared.global [%0], [%1], 16;\n" :: "r"(s), "l"(gmem));
}
__device__ __forceinline__ void cp_commit() { asm volatile("cp.async.commit_group;\n"); }
template <int N>
__device__ __forceinline__ void cp_wait() { asm volatile("cp.async.wait_group %0;\n" :: "n"(N)); }

__device__ __forceinline__ void mma_f16(float* c, const uint32_t* a, const uint32_t* b) {
    asm volatile("mma.sync.aligned.m16n8k16.row.col.f32.f16.f16.f32 "
        "{%0,%1,%2,%3}, {%4,%5,%6,%7}, {%8,%9}, {%0,%1,%2,%3};\n"
        : "+f"(c[0]), "+f"(c[1]), "+f"(c[2]), "+f"(c[3])
        : "r"(a[0]), "r"(a[1]), "r"(a[2]), "r"(a[3]), "r"(b[0]), "r"(b[1]));
}
__device__ __forceinline__ void ldsm_x4(uint32_t& r0, uint32_t& r1, uint32_t& r2, uint32_t& r3,
                                        uint32_t addr) {
    asm volatile("ldmatrix.sync.aligned.m8n8.x4.shared.b16 {%0,%1,%2,%3}, [%4];"
        : "=r"(r0), "=r"(r1), "=r"(r2), "=r"(r3) : "r"(addr));
}
// swizzled segment offset (halves): row r, 8-half chunk c (BK=16 -> c in {0,1})
__device__ __forceinline__ int swz16(int r, int c) {
    return r * 16 + ((c ^ ((r >> 2) & 1)) << 3);
}

// ---------------- epilogue functors (pairwise: cols n, n+1) --------------------
struct Epi1 {  // layer1 GEMM1: h1s = probs1 * gelu(v + b1) -> split half pair
    const float* b1;
    __device__ void operator()(int m, int n, float v0, float v1) const {
        int e = n >> 10, h = n & 1023;
        float p = g_P1[m * NE + e];
        float w0 = gelu_f(v0 + b1[e * DH + h]) * p;
        float w1 = gelu_f(v1 + b1[e * DH + h + 1]) * p;
        __half h0, l0, h1, l1;
        split16(w0, h0, l0); split16(w1, h1, l1);
        *(__half2*)(g_Hh + (size_t)m * KH + n) = __halves2half2(h0, h1);
        *(__half2*)(g_Hl + (size_t)m * KH + n) = __halves2half2(l0, l1);
    }
};
struct Epi2 {  // layer1 GEMM2: y = gelu(v + sum_e p*b2) -> fp32 + half
    const float* b2;
    __device__ void operator()(int m, int n, float v0, float v1) const {
        float ba = 0.f, bb = 0.f;
        #pragma unroll
        for (int e = 0; e < NE; e++) {
            float p = g_P1[m * NE + e];
            ba += p * b2[e * DMID + n];
            bb += p * b2[e * DMID + n + 1];
        }
        float y0 = gelu_f(v0 + ba), y1 = gelu_f(v1 + bb);
        g_Y[m * DMID + n] = y0;
        g_Y[m * DMID + n + 1] = y1;
        *(__half2*)(g_Yh + m * DMID + n) =
            __halves2half2(__float2half_rn(y0), __float2half_rn(y1));
    }
};
struct Epi3 {  // layer2 GEMM1: h2s = coef * gelu(v + b1) -> single half
    const float* b1;
    __device__ void operator()(int m, int n, float v0, float v1) const {
        int e = n >> 10, h = n & 1023;
        float c = g_coef[m * NE + e];
        float w0 = gelu_f(v0 + b1[e * DH + h]) * c;
        float w1 = gelu_f(v1 + b1[e * DH + h + 1]) * c;
        *(__half2*)(g_Hh + (size_t)m * KH + n) =
            __halves2half2(__float2half_rn(w0), __float2half_rn(w1));
    }
};
struct Epi4 {  // layer2 GEMM2: out = v + sum_e coef*b2 (only n < DOUT written)
    const float* b2;
    float* out;
    __device__ void operator()(int m, int n, float v0, float v1) const {
        #pragma unroll
        for (int t = 0; t < 2; t++) {
            int nn = n + t;
            float vv = t ? v1 : v0;
            if (nn < DOUT) {
                float bias = 0.f;
                #pragma unroll
                for (int e = 0; e < NE; e++) bias += g_coef[m * NE + e] * b2[e * DOUT + nn];
                out[(size_t)m * DOUT + nn] = vv + bias;
            }
        }
    }
};

// ---------------- fp16 tensor-core GEMM (single or scaled-residual x3) ---------
// C[m,n] = sum_k A[m,k]*B[n,k] (B stored n-major [n][k], N padded to tile mult).
// SPLIT: acc1 += Ah*Bh ; acc2 += Ah*Bl + Al*Bh ; final = acc1 + acc2*2^-11.
// BK=16, XOR-swizzled smem (no padding). NSTG-stage cp.async pipeline with a
// SINGLE __syncthreads per iteration: wait -> barrier -> issue next load ->
// compute. The load issued at iter kt writes stage (kt-1)%NSTG whose readers
// all passed the barrier; compute reads stage kt%NSTG (disjoint). One commit
// per iteration (empty in the tail) keeps the pending-group count invariant.
template <int BM, int BN, int BK, int WM, int WN, int NSTG, bool SPLIT, bool DRAIN, class Epi>
__global__ void __launch_bounds__(256) gemm_f16k(
    const __half* __restrict__ Ah_, const __half* __restrict__ Al_, int lda,
    const __half* __restrict__ Bh_, const __half* __restrict__ Bl_, int ldb,
    size_t e_stride, int e_shift, int K, Epi epi)
{
    static_assert(BK == 16, "swizzle hardcoded for BK=16");
    constexpr int WTM = BM / WM, WTN = BN / WN;
    constexpr int MT = WTM / 16, NT = WTN / 8;
    static_assert(NT % 2 == 0, "B ldmatrix pairs two n-tiles");
    constexpr int oAl = BM * BK;
    constexpr int oBh = (SPLIT ? 2 : 1) * BM * BK;
    constexpr int oBl = oBh + BN * BK;
    constexpr int SH = (SPLIT ? 2 : 1) * (BM + BN) * BK;   // halves per stage
    static_assert(NSTG * SH * 2 < 49152, "must fit under default 48KB smem");

    extern __shared__ __align__(16) __half sm[];
    const uint32_t smem_u32 = (uint32_t)__cvta_generic_to_shared(sm);

    const int tid = threadIdx.x, wid = tid >> 5, lane = tid & 31;
    const int wm = wid % WM, wn = wid / WM;
    const int qr = lane >> 2, qc = lane & 3;
    const int bm0 = blockIdx.x * BM, bn0 = blockIdx.y * BN;
    const int e = bn0 >> e_shift;
    const int nloc0 = bn0 - (e << e_shift);
    const __half* __restrict__ ApH = Ah_ + (size_t)bm0 * lda;
    const __half* __restrict__ ApL = SPLIT ? (Al_ + (size_t)bm0 * lda) : Ah_;
    const __half* __restrict__ BpH = Bh_ + (size_t)e * e_stride + (size_t)nloc0 * ldb;
    const __half* __restrict__ BpL = SPLIT ? (Bl_ + (size_t)e * e_stride + (size_t)nloc0 * ldb) : Bh_;

    // per-lane ldmatrix addressing
    const int a_row = wm * WTM + (lane & 15);
    const int a_chk = (lane & 16) ? 1 : 0;
    const int b_row = wn * WTN + (lane & 7) + ((lane & 16) ? 8 : 0);
    const int b_chk = (lane & 8) ? 1 : 0;

    float acc1[MT][NT][4], acc2[MT][NT][4];
    float accM[DRAIN ? MT : 1][DRAIN ? NT : 1][4];
    #pragma unroll
    for (int i = 0; i < MT; i++)
        #pragma unroll
        for (int j = 0; j < NT; j++)
            #pragma unroll
            for (int r = 0; r < 4; r++) { acc1[i][j][r] = 0.f; acc2[i][j][r] = 0.f; }
    if constexpr (DRAIN) {
        #pragma unroll
        for (int i = 0; i < MT; i++)
            #pragma unroll
            for (int j = 0; j < NT; j++)
                #pragma unroll
                for (int r = 0; r < 4; r++) accM[i][j][r] = 0.f;
    }

    auto load_stage = [&](int kt, int st) {
        const int k0 = kt * BK;
        __half* base = sm + st * SH;
        constexpr int AQ = BM * 2;       // 2 chunks of 8 halves per row
        #pragma unroll
        for (int it = 0; it < (AQ + 255) / 256; ++it) {
            int idx = tid + it * 256;
            if (AQ % 256 == 0 || idx < AQ) {
                int r = idx >> 1, c = idx & 1;
                int doff = swz16(r, c);
                size_t s = (size_t)r * lda + k0 + c * 8;
                cp16(base + doff, ApH + s);
                if constexpr (SPLIT) cp16(base + oAl + doff, ApL + s);
            }
        }
        constexpr int BQ = BN * 2;
        #pragma unroll
        for (int it = 0; it < (BQ + 255) / 256; ++it) {
            int idx = tid + it * 256;
            if (BQ % 256 == 0 || idx < BQ) {
                int r = idx >> 1, c = idx & 1;
                int doff = swz16(r, c);
                size_t s = (size_t)r * ldb + k0 + c * 8;
                cp16(base + oBh + doff, BpH + s);
                if constexpr (SPLIT) cp16(base + oBl + doff, BpL + s);
            }
        }
        cp_commit();
    };

    const int KT = K / BK;
    // prologue: fill NSTG-1 stages (pad with empty groups if KT is small)
    #pragma unroll 1
    for (int s = 0; s < NSTG - 1; ++s) {
        if (s < KT) load_stage(s, s);
        else        cp_commit();
    }
    for (int kt = 0; kt < KT; ++kt) {
        cp_wait<NSTG - 2>();       // tile kt's group (and older) complete
        __syncthreads();           // all warps see stage kt; stage (kt-1) free
        // issue next load (writes stage (kt-1)%NSTG); overlaps with compute
        if (kt + NSTG - 1 < KT) load_stage(kt + NSTG - 1, (kt + NSTG - 1) % NSTG);
        else                    cp_commit();
        const uint32_t stage_u32 = smem_u32 + (uint32_t)((kt % NSTG) * SH) * 2u;
        {
            uint32_t ah[MT][4], al[MT][4], bh[NT][2], bl[NT][2];
            #pragma unroll
            for (int mt = 0; mt < MT; ++mt) {
                int r = a_row + mt * 16;
                uint32_t off = stage_u32 + 2u * (uint32_t)swz16(r, a_chk);
                ldsm_x4(ah[mt][0], ah[mt][1], ah[mt][2], ah[mt][3], off);
                if constexpr (SPLIT)
                    ldsm_x4(al[mt][0], al[mt][1], al[mt][2], al[mt][3], off + 2u * oAl);
            }
            #pragma unroll
            for (int j = 0; j < NT / 2; ++j) {
                int r = b_row + j * 16;
                uint32_t off = stage_u32 + 2u * (uint32_t)(oBh + swz16(r, b_chk));
                ldsm_x4(bh[2 * j][0], bh[2 * j][1], bh[2 * j + 1][0], bh[2 * j + 1][1], off);
                if constexpr (SPLIT)
                    ldsm_x4(bl[2 * j][0], bl[2 * j][1], bl[2 * j + 1][0], bl[2 * j + 1][1],
                            off + 2u * (uint32_t)(oBl - oBh));
            }
            #pragma unroll
            for (int mt = 0; mt < MT; ++mt)
                #pragma unroll
                for (int nt = 0; nt < NT; ++nt) {
                    mma_f16(acc1[mt][nt], ah[mt], bh[nt]);
                    if constexpr (SPLIT) {
                        mma_f16(acc2[mt][nt], ah[mt], bl[nt]);
                        mma_f16(acc2[mt][nt], al[mt], bh[nt]);
                    }
                }
        }
        if constexpr (DRAIN) {
            if ((kt & 63) == 63) {
                #pragma unroll
                for (int i = 0; i < MT; i++)
                    #pragma unroll
                    for (int j = 0; j < NT; j++)
                        #pragma unroll
                        for (int r = 0; r < 4; r++) {
                            accM[i][j][r] += acc1[i][j][r] + (SPLIT ? acc2[i][j][r] * RINV : 0.f);
                            acc1[i][j][r] = 0.f; acc2[i][j][r] = 0.f;
                        }
            }
        }
    }

    #pragma unroll
    for (int mt = 0; mt < MT; ++mt)
        #pragma unroll
        for (int nt = 0; nt < NT; ++nt) {
            float f[4];
            #pragma unroll
            for (int i = 0; i < 4; i++) {
                if constexpr (DRAIN)
                    f[i] = accM[mt][nt][i] + acc1[mt][nt][i] + (SPLIT ? acc2[mt][nt][i] * RINV : 0.f);
                else if constexpr (SPLIT)
                    f[i] = acc1[mt][nt][i] + acc2[mt][nt][i] * RINV;
                else
                    f[i] = acc1[mt][nt][i];
            }
            int row = bm0 + wm * WTM + mt * 16 + qr;
            int col = bn0 + wn * WTN + nt * 8 + qc * 2;
            epi(row, col, f[0], f[1]);
            epi(row + 8, col, f[2], f[3]);
        }
}

// ---------------- prep kernels --------------------------------------------------
__global__ void w1_tsplit_f16(const float* __restrict__ w1) {  // [e][d][h] -> [e][h][d] hi/lo
    __shared__ float t[32][33];
    int e = blockIdx.z, d0 = blockIdx.x * 32, h0 = blockIdx.y * 32;
    const float* src = w1 + ((size_t)e * DIN + d0) * DH + h0;
    for (int dy = threadIdx.y; dy < 32; dy += 8)
        t[dy][threadIdx.x] = src[(size_t)dy * DH + threadIdx.x];
    __syncthreads();
    __half* dh = g_W1th + ((size_t)e * DH + h0) * DIN + d0;
    __half* dl = g_W1tl + ((size_t)e * DH + h0) * DIN + d0;
    for (int hy = threadIdx.y; hy < 32; hy += 8) {
        __half hh, hl;
        split16(t[threadIdx.x][hy], hh, hl);
        dh[(size_t)hy * DIN + threadIdx.x] = hh;
        dl[(size_t)hy * DIN + threadIdx.x] = hl;
    }
}
// merged prep for W2 (hi/lo), W3 (single), W4 (single, padded)
__global__ void wmisc_f16(const float* __restrict__ w2, const float* __restrict__ w3,
                          const float* __restrict__ w4) {
    const int N2 = DMID * KH;
    const int N3 = NE * DH * DMID;
    const int N4 = DOUT * KH;
    int i = blockIdx.x * blockDim.x + threadIdx.x;
    if (i < N2) {
        int n = i / KH, k = i % KH;
        __half h, l;
        split16(w2[(size_t)k * DMID + n], h, l);
        g_W2th[i] = h; g_W2tl[i] = l;
    }
    if (i < N3) {
        int d = i % DMID, eh = i / DMID;
        int e = eh >> 10, h = eh & 1023;
        g_W3t[i] = __float2half_rn(w3[((size_t)e * DMID + d) * DH + h]);
    }
    if (i < N4) {
        int n = i / KH, k = i % KH;
        int e = k >> 10, h = k & 1023;
        g_W4t[i] = __float2half_rn(w4[((size_t)e * DH + h) * DOUT + n]);
    }
}
__global__ void concat_split_f16(const float* __restrict__ x8, const float* __restrict__ x16,
                                 const float* __restrict__ x32) {
    const int total = NB * DIN;
    for (int i = blockIdx.x * blockDim.x + threadIdx.x; i < total; i += gridDim.x * blockDim.x) {
        int b = i / DIN, j = i % DIN;
        float v = (j < 64) ? x8[b * 64 + j]
                : (j < 320) ? x16[b * 256 + (j - 64)]
                            : x32[b * 1024 + (j - 320)];
        __half h, l;
        split16(v, h, l);
        g_Xh[i] = h; g_Xl[i] = l;
    }
}

// ---------------- routing / aux -------------------------------------------------
__global__ void gate1_kernel(const float* __restrict__ gw, const float* __restrict__ gb) {
    int row = blockIdx.x * 8 + (threadIdx.x >> 5), lane = threadIdx.x & 31;
    if (row >= NB) return;
    float acc[NE];
    #pragma unroll
    for (int e = 0; e < NE; e++) acc[e] = 0.f;
    const __half* xh = g_Xh + (size_t)row * DIN;
    const __half* xl = g_Xl + (size_t)row * DIN;
    for (int d = lane; d < DIN; d += 32) {
        float xv = __half2float(xh[d]) + __half2float(xl[d]) * RINV;
        const float4* w4 = (const float4*)(gw + d * NE);
        float4 w0 = w4[0], w1 = w4[1];
        acc[0] += xv * w0.x; acc[1] += xv * w0.y; acc[2] += xv * w0.z; acc[3] += xv * w0.w;
        acc[4] += xv * w1.x; acc[5] += xv * w1.y; acc[6] += xv * w1.z; acc[7] += xv * w1.w;
    }
    #pragma unroll
    for (int o = 16; o; o >>= 1)
        #pragma unroll
        for (int e = 0; e < NE; e++) acc[e] += __shfl_xor_sync(0xffffffffu, acc[e], o);
    if (lane == 0) {
        float mx = -1e30f;
        #pragma unroll
        for (int e = 0; e < NE; e++) { acc[e] += gb[e]; mx = fmaxf(mx, acc[e]); }
        float s = 0.f;
        #pragma unroll
        for (int e = 0; e < NE; e++) { acc[e] = expf(acc[e] - mx); s += acc[e]; }
        float inv = 1.f / s;
        #pragma unroll
        for (int e = 0; e < NE; e++) g_P1[row * NE + e] = acc[e] * inv;
    }
}
__global__ void gate2_kernel(const float* __restrict__ gw) {
    int row = blockIdx.x * 8 + (threadIdx.x >> 5), lane = threadIdx.x & 31;
    if (row >= NB) return;
    float acc[NE];
    #pragma unroll
    for (int e = 0; e < NE; e++) acc[e] = 0.f;
    const float* y = g_Y + (size_t)row * DMID;
    #pragma unroll
    for (int it = 0; it < DMID / 32; it++) {
        int o = lane + it * 32;
        float yv = y[o];
        const float4* w4 = (const float4*)(gw + o * NE);
        float4 w0 = w4[0], w1 = w4[1];
        acc[0] += yv * w0.x; acc[1] += yv * w0.y; acc[2] += yv * w0.z; acc[3] += yv * w0.w;
        acc[4] += yv * w1.x; acc[5] += yv * w1.y; acc[6] += yv * w1.z; acc[7] += yv * w1.w;
    }
    #pragma unroll
    for (int o = 16; o; o >>= 1)
        #pragma unroll
        for (int e = 0; e < NE; e++) acc[e] += __shfl_xor_sync(0xffffffffu, acc[e], o);
    if (lane == 0) {
        float mx = -1e30f;
        #pragma unroll
        for (int e = 0; e < NE; e++) mx = fmaxf(mx, acc[e]);
        float s = 0.f;
        #pragma unroll
        for (int e = 0; e < NE; e++) { acc[e] = expf(acc[e] - mx); s += acc[e]; }
        float inv = 1.f / s;
        #pragma unroll
        for (int e = 0; e < NE; e++) { acc[e] *= inv; g_probs2[row * NE + e] = acc[e]; }
        int i1 = 0;
        #pragma unroll
        for (int e = 1; e < NE; e++) if (acc[e] > acc[i1]) i1 = e;
        int i2 = (i1 == 0) ? 1 : 0;
        #pragma unroll
        for (int e = 0; e < NE; e++) if (e != i1 && acc[e] > acc[i2]) i2 = e;
        float r = 1.f / (acc[i1] + acc[i2] + 1e-6f);
        #pragma unroll
        for (int e = 0; e < NE; e++)
            g_coef[row * NE + e] = (e == i1) ? acc[i1] * r : ((e == i2) ? acc[i2] * r : 0.f);
    }
}
__global__ void aux_kernel(float* __restrict__ out) {
    __shared__ float s_sum[256], s_cnt[256];
    int t = threadIdx.x, e = t & 7, chunk = t >> 3;
    float sum = 0.f, cnt = 0.f;
    for (int b = chunk; b < NB; b += 32) {
        sum += g_probs2[b * NE + e];
        cnt += (g_coef[b * NE + e] > 0.f) ? 1.f : 0.f;
    }
    s_sum[t] = sum; s_cnt[t] = cnt;
    __syncthreads();
    for (int s = 128; s >= 8; s >>= 1) {
        if (t < s) { s_sum[t] += s_sum[t + s]; s_cnt[t] += s_cnt[t + s]; }
        __syncthreads();
    }
    if (t == 0) {
        float aux = 0.f;
        #pragma unroll
        for (int ee = 0; ee < NE; ee++)
            aux += (s_sum[ee] / (float)NB) * (s_cnt[ee] / (float)(NB * 2));
        out[(size_t)NB * DOUT] = (float)NE * aux;
    }
}

// ---------------- launch --------------------------------------------------------
extern "C" void kernel_launch(void* const* d_in, const int* in_sizes, int n_in,
                              void* d_out, int out_size) {
    const float* x8   = (const float*)d_in[0];
    const float* x16  = (const float*)d_in[1];
    const float* x32  = (const float*)d_in[2];
    const float* g1w  = (const float*)d_in[3];
    const float* g1b  = (const float*)d_in[4];
    const float* e1w1 = (const float*)d_in[5];
    const float* e1b1 = (const float*)d_in[6];
    const float* e1w2 = (const float*)d_in[7];
    const float* e1b2 = (const float*)d_in[8];
    const float* g2w  = (const float*)d_in[9];
    const float* e2w1 = (const float*)d_in[10];
    const float* e2b1 = (const float*)d_in[11];
    const float* e2w2 = (const float*)d_in[12];
    const float* e2b2 = (const float*)d_in[13];
    float* out = (float*)d_out;

    __half *Xh, *Xl, *W1h, *W1l, *W2h, *W2l, *W3, *W4, *Hh, *Hl, *Yh;
    cudaGetSymbolAddress((void**)&Xh,  g_Xh);
    cudaGetSymbolAddress((void**)&Xl,  g_Xl);
    cudaGetSymbolAddress((void**)&W1h, g_W1th);
    cudaGetSymbolAddress((void**)&W1l, g_W1tl);
    cudaGetSymbolAddress((void**)&W2h, g_W2th);
    cudaGetSymbolAddress((void**)&W2l, g_W2tl);
    cudaGetSymbolAddress((void**)&W3,  g_W3t);
    cudaGetSymbolAddress((void**)&W4,  g_W4t);
    cudaGetSymbolAddress((void**)&Hh,  g_Hh);
    cudaGetSymbolAddress((void**)&Hl,  g_Hl);
    cudaGetSymbolAddress((void**)&Yh,  g_Yh);

    // prep needed by GEMM1 first; GEMM1 early for ncu capture window
    w1_tsplit_f16<<<dim3(DIN / 32, DH / 32, NE), dim3(32, 8)>>>(e1w1);       // 0
    concat_split_f16<<<1024, 256>>>(x8, x16, x32);                           // 1
    gate1_kernel<<<NB / 8, 256>>>(g1w, g1b);                                 // 2

    // layer1 GEMM1 (fp16x3, 3-stage, 128x64 BK16, swizzled): smem 36864
    gemm_f16k<128, 64, 16, 4, 2, 3, true, false, Epi1><<<dim3(NB / 128, KH / 64), 256, 36864>>>(
        Xh, Xl, DIN, W1h, W1l, DIN, (size_t)DH * DIN, 10, DIN, Epi1{e1b1});  // 3

    wmisc_f16<<<(DOUT * KH + 255) / 256, 256>>>(e1w2, e2w1, e2w2);           // 4

    // layer1 GEMM2 (fp16x3 + drain, 4-stage, 64x64 BK16): smem 32768
    gemm_f16k<64, 64, 16, 2, 4, 4, true, true, Epi2><<<dim3(NB / 64, DMID / 64), 256, 32768>>>(
        Hh, Hl, KH, W2h, W2l, KH, 0, 30, KH, Epi2{e1b2});                    // 5

    gate2_kernel<<<NB / 8, 256>>>(g2w);                                      // 6

    // layer2 GEMM1 (fp16 single, 4-stage, 128x64 BK16): smem 24576
    gemm_f16k<128, 64, 16, 4, 2, 4, false, false, Epi3><<<dim3(NB / 128, KH / 64), 256, 24576>>>(
        Yh, Yh, DMID, W3, W3, DMID, (size_t)DH * DMID, 10, DMID, Epi3{e2b1});

    // layer2 GEMM2 (fp16 single, 4-stage, 64x64 BK16): smem 16384
    gemm_f16k<64, 64, 16, 2, 4, 4, false, false, Epi4><<<dim3(NB / 64, DOUTP / 64), 256, 16384>>>(
        Hh, Hh, KH, W4, W4, KH, 0, 30, KH, Epi4{e2b2, out});

    aux_kernel<<<1, 256>>>(out);
}